// round 3
// baseline (speedup 1.0000x reference)
#include <cuda_runtime.h>
#include <math.h>

#define PTS    4096
#define BATCH  32
#define TPB    256
#define QTILES (PTS / TPB)              // 16 query tiles per (dir, batch)
#define NPART  (2 * BATCH * QTILES)     // 1024 block partials
#define SMEM_BYTES (PTS * 16)           // 4096 float4 = 64KB

// Sorted point sets (by x ascending), packed {x, y, z, |p|^2}.
__device__ float4 g_sortP[BATCH * PTS];
__device__ float4 g_sortG[BATCH * PTS];
__device__ float  g_partial[NPART];

// ---------------------------------------------------------------------------
// Kernel 1: per (batch, set) in-smem bitonic sort by x. Grid (BATCH, 2).
// ---------------------------------------------------------------------------
__global__ __launch_bounds__(1024) void sort_kernel(
    const float* __restrict__ pred, const float* __restrict__ gt)
{
    extern __shared__ float4 ss[];   // 4096 float4
    const int b   = blockIdx.x;
    const int set = blockIdx.y;      // 0: pred, 1: gt
    const int tid = threadIdx.x;

    const float* __restrict__ src = (set ? gt : pred) + (size_t)b * PTS * 3;
    for (int i = tid; i < PTS; i += 1024) {
        float x = src[3 * i], y = src[3 * i + 1], z = src[3 * i + 2];
        ss[i] = make_float4(x, y, z, fmaf(x, x, fmaf(y, y, z * z)));
    }
    __syncthreads();

    // Bitonic sort ascending by .x
    for (int k = 2; k <= PTS; k <<= 1) {
        for (int s = k >> 1; s > 0; s >>= 1) {
            for (int i = tid; i < PTS; i += 1024) {
                int j = i ^ s;
                if (j > i) {
                    float4 a  = ss[i];
                    float4 bb = ss[j];
                    bool up = ((i & k) == 0);
                    if ((a.x > bb.x) == up) { ss[i] = bb; ss[j] = a; }
                }
            }
            __syncthreads();
        }
    }

    float4* __restrict__ dst = (set ? g_sortG : g_sortP) + (size_t)b * PTS;
    for (int i = tid; i < PTS; i += 1024) dst[i] = ss[i];
}

// ---------------------------------------------------------------------------
// Kernel 2: windowed nearest-neighbor scan.
//   dir 0: query = gt (sortedG), target = pred (sortedP)   -> chamfer1
//   dir 1: query = pred,          target = gt              -> chamfer2
// Targets staged in smem scaled: {-2x, -2y, -2z, |g|^2}, so
//   t = fmaf(pz,gz', fmaf(py,gy', fmaf(px,gx', g2))) = d2 - p2.
// Warp scans a shared contiguous window outward from lane0's rank; a side
// terminates when ALL lanes certify frontier dx^2 > best d2 (with sign guard).
// ---------------------------------------------------------------------------
__global__ __launch_bounds__(TPB) void chamfer_win_kernel()
{
    extern __shared__ float4 st[];   // 4096 scaled targets

    const int qt  = blockIdx.x;
    const int b   = blockIdx.y;
    const int dir = blockIdx.z;

    const float4* __restrict__ qry = (dir ? g_sortP : g_sortG) + (size_t)b * PTS;
    const float4* __restrict__ tgt = (dir ? g_sortG : g_sortP) + (size_t)b * PTS;

    for (int i = threadIdx.x; i < PTS; i += TPB) {
        float4 g = tgt[i];
        st[i] = make_float4(-2.0f * g.x, -2.0f * g.y, -2.0f * g.z, g.w);
    }
    __syncthreads();

    const unsigned FULL = 0xFFFFFFFFu;
    const int lane = threadIdx.x & 31;

    const float4 qp = qry[qt * TPB + threadIdx.x];
    const float px = qp.x, py = qp.y, pz = qp.z, p2 = qp.w;

    // lane0 binary search: first index with target_x >= px.
    // st.x = -2*target_x is DESCENDING; advance while st[mid].x > -2*px.
    int c = 0;
    if (lane == 0) {
        const float key = -2.0f * px;
        int lo = 0, hi = PTS;
        while (lo < hi) {
            int mid = (lo + hi) >> 1;
            if (st[mid].x > key) lo = mid + 1; else hi = mid;
        }
        c = lo;
    }
    c = __shfl_sync(FULL, c, 0);

    float bt = 3.0e38f;              // best (d2 - p2)
    int L = c, R = c;                // next-left exclusive / next-right inclusive
    bool lact = (L > 0), ract = (R < PTS);

    while (lact || ract) {
        if (lact) {
            int j0 = L - 32; if (j0 < 0) j0 = 0;
            #pragma unroll 4
            for (int j = j0; j < L; ++j) {
                float4 g = st[j];
                float t = fmaf(pz, g.z, fmaf(py, g.y, fmaf(px, g.x, g.w)));
                bt = fminf(bt, t);
            }
            L = j0;
            if (L == 0) {
                lact = false;
            } else {
                float thresh = bt + p2;                 // best d2
                float fx = -0.5f * st[L - 1].x;         // frontier target x
                float dx = px - fx;
                bool done = (dx > 0.0f) && (dx * dx > thresh);
                lact = !__all_sync(FULL, done);
            }
        }
        if (ract) {
            int j1 = R + 32; if (j1 > PTS) j1 = PTS;
            #pragma unroll 4
            for (int j = R; j < j1; ++j) {
                float4 g = st[j];
                float t = fmaf(pz, g.z, fmaf(py, g.y, fmaf(px, g.x, g.w)));
                bt = fminf(bt, t);
            }
            R = j1;
            if (R >= PTS) {
                ract = false;
            } else {
                float thresh = bt + p2;
                float fx = -0.5f * st[R].x;
                float dx = fx - px;
                bool done = (dx > 0.0f) && (dx * dx > thresh);
                ract = !__all_sync(FULL, done);
            }
        }
    }

    float d2   = bt + p2;
    float dist = sqrtf(fmaxf(d2, 1e-12f));

    // Block sum reduction
    #pragma unroll
    for (int o = 16; o > 0; o >>= 1)
        dist += __shfl_down_sync(FULL, dist, o);

    __shared__ float wsum[TPB / 32];
    const int wid = threadIdx.x >> 5;
    if (lane == 0) wsum[wid] = dist;
    __syncthreads();

    if (threadIdx.x < TPB / 32) {
        float v = wsum[threadIdx.x];
        #pragma unroll
        for (int o = (TPB / 32) / 2; o > 0; o >>= 1)
            v += __shfl_down_sync(FULL, v, o, TPB / 32);
        if (threadIdx.x == 0)
            g_partial[(dir * BATCH + b) * QTILES + qt] = v;
    }
}

// ---------------------------------------------------------------------------
// Kernel 3: reduce NPART partials -> scalar mean.
// ---------------------------------------------------------------------------
__global__ void chamfer_finalize_kernel(float* __restrict__ out)
{
    float v = g_partial[threadIdx.x];
    const unsigned FULL = 0xFFFFFFFFu;
    #pragma unroll
    for (int o = 16; o > 0; o >>= 1)
        v += __shfl_down_sync(FULL, v, o);

    __shared__ float wsum[NPART / 32];
    const int lane = threadIdx.x & 31;
    const int wid  = threadIdx.x >> 5;
    if (lane == 0) wsum[wid] = v;
    __syncthreads();

    if (threadIdx.x < 32) {
        float t = (threadIdx.x < NPART / 32) ? wsum[threadIdx.x] : 0.0f;
        #pragma unroll
        for (int o = 16; o > 0; o >>= 1)
            t += __shfl_down_sync(FULL, t, o);
        if (threadIdx.x == 0)
            out[0] = t * (1.0f / (float)(BATCH * PTS));
    }
}

extern "C" void kernel_launch(void* const* d_in, const int* in_sizes, int n_in,
                              void* d_out, int out_size)
{
    (void)in_sizes; (void)n_in; (void)out_size;
    const float* pred = (const float*)d_in[0];
    const float* gt   = (const float*)d_in[1];
    float* out        = (float*)d_out;

    cudaFuncSetAttribute(sort_kernel,
                         cudaFuncAttributeMaxDynamicSharedMemorySize, SMEM_BYTES);
    cudaFuncSetAttribute(chamfer_win_kernel,
                         cudaFuncAttributeMaxDynamicSharedMemorySize, SMEM_BYTES);

    dim3 sgrid(BATCH, 2);
    sort_kernel<<<sgrid, 1024, SMEM_BYTES>>>(pred, gt);

    dim3 grid(QTILES, BATCH, 2);
    chamfer_win_kernel<<<grid, TPB, SMEM_BYTES>>>();

    chamfer_finalize_kernel<<<1, NPART>>>(out);
}

// round 4
// speedup vs baseline: 1.4224x; 1.4224x over previous
#include <cuda_runtime.h>
#include <math.h>

#define PTS    4096
#define BATCH  32
#define TPB    256
#define NB     256                       // x-buckets per (set,batch)
#define QTILES (PTS / TPB)               // 16 query tiles per (dir,batch)
#define NPART  (2 * BATCH * QTILES)      // 1024 block partials
#define SMEM_SCAN (PTS * 16)             // 64KB dynamic: staged targets

// Bucket-ordered point sets, pre-scaled {-2x, -2y, -2z, |p|^2}.
__device__ float4 g_sA[BATCH * PTS];     // pred (set 0)
__device__ float4 g_sB[BATCH * PTS];     // gt   (set 1)
__device__ int    g_cdf[2 * BATCH * (NB + 1)];
__device__ float4 g_meta[2 * BATCH];     // {x0, w, invw, 0}
__device__ float  g_partial[NPART];

// ---------------------------------------------------------------------------
// Kernel 1: per (batch,set) bucket counting-sort by x. Grid (BATCH, 2), 256 thr.
// ---------------------------------------------------------------------------
__global__ __launch_bounds__(TPB) void bucket_kernel(
    const float* __restrict__ pred, const float* __restrict__ gt)
{
    __shared__ unsigned hist[NB];
    __shared__ unsigned offs[NB];
    __shared__ unsigned wscan[8];
    __shared__ float    red[64];
    __shared__ float    sx0, sinvw, sw;

    const int b   = blockIdx.x;
    const int set = blockIdx.y;
    const int tid = threadIdx.x;
    const unsigned FULL = 0xFFFFFFFFu;
    const int lane = tid & 31, wid = tid >> 5;

    const float* __restrict__ src = (set ? gt : pred) + (size_t)b * PTS * 3;

    // ---- pass 1: min/max of x ----
    float mn = 3.0e38f, mx = -3.0e38f;
    for (int i = tid; i < PTS; i += TPB) {
        float x = src[3 * i];
        mn = fminf(mn, x); mx = fmaxf(mx, x);
    }
    #pragma unroll
    for (int o = 16; o > 0; o >>= 1) {
        mn = fminf(mn, __shfl_xor_sync(FULL, mn, o));
        mx = fmaxf(mx, __shfl_xor_sync(FULL, mx, o));
    }
    if (lane == 0) { red[wid] = mn; red[32 + wid] = mx; }
    __syncthreads();
    if (tid == 0) {
        float a = red[0], c = red[32];
        #pragma unroll
        for (int i = 1; i < 8; i++) { a = fminf(a, red[i]); c = fmaxf(c, red[32 + i]); }
        float w = fmaxf(c - a, 1e-30f) / (float)NB;
        sx0 = a; sw = w; sinvw = 1.0f / w;
    }
    hist[tid] = 0;
    __syncthreads();
    const float x0 = sx0, invw = sinvw, w = sw;

    // ---- pass 2: histogram ----
    for (int i = tid; i < PTS; i += TPB) {
        float x = src[3 * i];
        int bk = (int)fminf(fmaxf((x - x0) * invw, 0.0f), (float)(NB - 1));
        atomicAdd(&hist[bk], 1u);
    }
    __syncthreads();

    // ---- exclusive scan over NB=256 ----
    unsigned v = hist[tid];
    unsigned inc = v;
    #pragma unroll
    for (int o = 1; o < 32; o <<= 1) {
        unsigned n = __shfl_up_sync(FULL, inc, o);
        if (lane >= o) inc += n;
    }
    if (lane == 31) wscan[wid] = inc;
    __syncthreads();
    if (wid == 0 && lane < 8) {
        unsigned wv = wscan[lane];
        #pragma unroll
        for (int o = 1; o < 8; o <<= 1) {
            unsigned n = __shfl_up_sync(0xFFu, wv, o);
            if (lane >= o) wv += n;
        }
        wscan[lane] = wv;
    }
    __syncthreads();
    unsigned excl = inc - v + (wid ? wscan[wid - 1] : 0u);
    offs[tid] = excl;

    const int base = (set * BATCH + b) * (NB + 1);
    g_cdf[base + tid] = (int)excl;
    if (tid == 0) {
        g_cdf[base + NB] = PTS;
        g_meta[set * BATCH + b] = make_float4(x0, w, invw, 0.0f);
    }
    __syncthreads();

    // ---- pass 3: scatter (pre-scaled) ----
    float4* __restrict__ dst = (set ? g_sB : g_sA) + (size_t)b * PTS;
    for (int i = tid; i < PTS; i += TPB) {
        float x = src[3 * i], y = src[3 * i + 1], z = src[3 * i + 2];
        int bk = (int)fminf(fmaxf((x - x0) * invw, 0.0f), (float)(NB - 1));
        unsigned pos = atomicAdd(&offs[bk], 1u);
        dst[pos] = make_float4(-2.0f * x, -2.0f * y, -2.0f * z,
                               fmaf(x, x, fmaf(y, y, z * z)));
    }
}

// ---------------------------------------------------------------------------
// Kernel 2: bucket-windowed NN scan. Grid (QTILES, BATCH, 2).
//   dir 0: query = gt, target = pred ; dir 1: query = pred, target = gt.
// ---------------------------------------------------------------------------
__global__ __launch_bounds__(TPB) void chamfer_scan_kernel()
{
    extern __shared__ float4 st[];          // 4096 scaled targets
    __shared__ int   scdf[NB + 1];
    __shared__ float sm[3];                 // x0, w, invw of TARGET set

    const int qt  = blockIdx.x;
    const int b   = blockIdx.y;
    const int dir = blockIdx.z;
    const int tid = threadIdx.x;
    const unsigned FULL = 0xFFFFFFFFu;
    const int lane = tid & 31;

    const int qset = dir ? 0 : 1;           // dir1: query pred
    const int tset = dir ? 1 : 0;
    const float4* __restrict__ qry = (qset ? g_sB : g_sA) + (size_t)b * PTS;
    const float4* __restrict__ tgt = (tset ? g_sB : g_sA) + (size_t)b * PTS;

    for (int i = tid; i < PTS; i += TPB) st[i] = tgt[i];
    for (int i = tid; i < NB + 1; i += TPB)
        scdf[i] = g_cdf[(tset * BATCH + b) * (NB + 1) + i];
    if (tid == 0) {
        float4 m = g_meta[tset * BATCH + b];
        sm[0] = m.x; sm[1] = m.y; sm[2] = m.z;
    }
    __syncthreads();
    const float x0 = sm[0], w = sm[1], invw = sm[2];

    // Query (stored scaled; recover coords).
    const float4 qp = qry[qt * TPB + tid];
    const float px = -0.5f * qp.x, py = -0.5f * qp.y, pz = -0.5f * qp.z;
    const float p2 = qp.w;

    int qb = (int)fminf(fmaxf((px - x0) * invw, 0.0f), (float)(NB - 1));
    int bmin = qb, bmax = qb;
    #pragma unroll
    for (int o = 16; o > 0; o >>= 1) {
        bmin = min(bmin, __shfl_xor_sync(FULL, bmin, o));
        bmax = max(bmax, __shfl_xor_sync(FULL, bmax, o));
    }

    float bt0 = 3.0e38f, bt1 = 3.0e38f;     // best (d2 - p2), 2 accumulators

    // Chunk-aligned scan of [lo, hi): guard-free unrolled body.
    #define SCAN_RANGE(LO, HI)                                                \
        for (int j0 = (LO); j0 < (HI); j0 += 32) {                            \
            _Pragma("unroll")                                                 \
            for (int u = 0; u < 32; u += 2) {                                 \
                float4 ga = st[j0 + u];                                       \
                float4 gb = st[j0 + u + 1];                                   \
                bt0 = fminf(bt0, fmaf(pz, ga.z, fmaf(py, ga.y, fmaf(px, ga.x, ga.w)))); \
                bt1 = fminf(bt1, fmaf(pz, gb.z, fmaf(py, gb.y, fmaf(px, gb.x, gb.w)))); \
            }                                                                 \
        }

    int SL = scdf[bmin] & ~31;                       // scanned-low (32-aligned)
    int SR = (scdf[bmax + 1] + 31) & ~31;            // scanned-high
    if (SR > PTS) SR = PTS;
    SCAN_RANGE(SL, SR);

    int  bl = bmin - 1, br = bmax + 1;
    bool lact = (bl >= 0), ract = (br < NB);

    while (lact || ract) {
        if (lact) {
            float edge = x0 + (float)(bl + 1) * w;   // right edge of bucket bl
            float dx = px - edge;
            float thr = bt0 < bt1 ? bt0 : bt1;
            bool done = (dx > 0.0f) && (dx * dx > thr + p2 + 1e-6f);
            if (__all_sync(FULL, done)) {
                lact = false;
            } else {
                int nl = scdf[bl] & ~31;
                SCAN_RANGE(nl, SL);
                SL = nl;
                if (--bl < 0) lact = false;
            }
        }
        if (ract) {
            float edge = x0 + (float)br * w;         // left edge of bucket br
            float dx = edge - px;
            float thr = bt0 < bt1 ? bt0 : bt1;
            bool done = (dx > 0.0f) && (dx * dx > thr + p2 + 1e-6f);
            if (__all_sync(FULL, done)) {
                ract = false;
            } else {
                int nh = (scdf[br + 1] + 31) & ~31;
                if (nh > PTS) nh = PTS;
                SCAN_RANGE(SR, nh);
                SR = nh;
                if (++br >= NB) ract = false;
            }
        }
    }
    #undef SCAN_RANGE

    float d2   = fminf(bt0, bt1) + p2;
    float dist = sqrtf(fmaxf(d2, 1e-12f));

    // Block sum reduction.
    #pragma unroll
    for (int o = 16; o > 0; o >>= 1)
        dist += __shfl_down_sync(FULL, dist, o);

    __shared__ float wsum[TPB / 32];
    const int wid = tid >> 5;
    if (lane == 0) wsum[wid] = dist;
    __syncthreads();
    if (tid < TPB / 32) {
        float v = wsum[tid];
        #pragma unroll
        for (int o = (TPB / 32) / 2; o > 0; o >>= 1)
            v += __shfl_down_sync(FULL, v, o, TPB / 32);
        if (tid == 0)
            g_partial[(dir * BATCH + b) * QTILES + qt] = v;
    }
}

// ---------------------------------------------------------------------------
// Kernel 3: reduce NPART=1024 partials -> scalar mean.
// ---------------------------------------------------------------------------
__global__ void chamfer_finalize_kernel(float* __restrict__ out)
{
    float v = g_partial[threadIdx.x];
    const unsigned FULL = 0xFFFFFFFFu;
    #pragma unroll
    for (int o = 16; o > 0; o >>= 1)
        v += __shfl_down_sync(FULL, v, o);

    __shared__ float wsum[32];
    const int lane = threadIdx.x & 31;
    const int wid  = threadIdx.x >> 5;
    if (lane == 0) wsum[wid] = v;
    __syncthreads();

    if (threadIdx.x < 32) {
        float t = wsum[threadIdx.x];
        #pragma unroll
        for (int o = 16; o > 0; o >>= 1)
            t += __shfl_down_sync(FULL, t, o);
        if (threadIdx.x == 0)
            out[0] = t * (1.0f / (float)(BATCH * PTS));
    }
}

extern "C" void kernel_launch(void* const* d_in, const int* in_sizes, int n_in,
                              void* d_out, int out_size)
{
    (void)in_sizes; (void)n_in; (void)out_size;
    const float* pred = (const float*)d_in[0];
    const float* gt   = (const float*)d_in[1];
    float* out        = (float*)d_out;

    cudaFuncSetAttribute(chamfer_scan_kernel,
                         cudaFuncAttributeMaxDynamicSharedMemorySize, SMEM_SCAN);

    dim3 bgrid(BATCH, 2);
    bucket_kernel<<<bgrid, TPB>>>(pred, gt);

    dim3 sgrid(QTILES, BATCH, 2);
    chamfer_scan_kernel<<<sgrid, TPB, SMEM_SCAN>>>();

    chamfer_finalize_kernel<<<1, NPART>>>(out);
}